// round 3
// baseline (speedup 1.0000x reference)
#include <cuda_runtime.h>
#include <cuda_bf16.h>
#include <cstddef>

// WKV2D: B=8, H=16, W=16, C=256.
// k_adj = sum_taps relu(k - w*manhattan_d) (+u bonus at center); out = exp(k_adj)*v.
// Sparsity: taps with d > r = floor(kmax_c/w_c)+1 are exactly zero.
// Halo trick: -1e30 padding => relu gives exact 0, no bounds checks.

#define B_DIM   8
#define C_DIM   256
#define PAD     3            // fast path covers r <= 3
#define TW      23           // odd row stride -> conflict-free tap LDS
#define TROWS   22           // 16 + 2*PAD
#define TILE    (TW * TROWS) // 506
#define CSTRIDE 512

__device__ __forceinline__ float relu_(float x) { return fmaxf(x, 0.0f); }

// 2 channels x 2 horizontally-adjacent pixels, compile-time radius.
// Row segments loaded once serve both pixels.
template<int R>
__device__ __forceinline__ void diamond22(const float* __restrict__ ks, int pos0,
                                          float wn0, float wn1, float acc[4])
{
    float wd0[2 * R + 1], wd1[2 * R + 1];
    #pragma unroll
    for (int d = 0; d <= 2 * R; ++d) { wd0[d] = wn0 * (float)d; wd1[d] = wn1 * (float)d; }

    #pragma unroll
    for (int di = -R; di <= R; ++di) {
        const int adi = di < 0 ? -di : di;
        const int rr  = R - adi;
        const int base = pos0 + di * TW - rr;
        #pragma unroll
        for (int j = 0; j <= 2 * rr + 1; ++j) {
            float s0 = ks[base + j];
            float s1 = ks[CSTRIDE + base + j];
            const int dA = adi + (j >= rr ? j - rr : rr - j);           // pixel0
            const int dB = adi + (j >= rr + 1 ? j - rr - 1 : rr + 1 - j); // pixel1
            if (j <= 2 * rr) {                 // valid tap for pixel0
                acc[0] += relu_(s0 + wd0[dA]);
                acc[2] += relu_(s1 + wd1[dA]);
            }
            if (j >= 1) {                      // valid tap for pixel1
                acc[1] += relu_(s0 + wd0[dB]);
                acc[3] += relu_(s1 + wd1[dB]);
            }
        }
    }
}

__global__ __launch_bounds__(128, 8)
void wkv2d_kernel(const float* __restrict__ w,
                  const float* __restrict__ u,
                  const float* __restrict__ k,
                  const float* __restrict__ v,
                  float* __restrict__ out)
{
    __shared__ float ks[2 * CSTRIDE];
    __shared__ float red[8];            // [c(2)][warp(4)]

    const int b  = blockIdx.x >> 7;     // 128 channel-pairs per batch
    const int cp = blockIdx.x & 127;
    const int c0 = cp * 2;
    const int t  = threadIdx.x;

    const size_t base = ((size_t)b * 256) * C_DIM + c0;

    // pixel-pair mapping: y = t>>3, x0 = 2*(t&7)
    const int y   = t >> 3;
    const int x0  = (t & 7) << 1;
    const int px0 = (y << 4) | x0;

    // ---- coalesced float2 loads (both channels of 2 adjacent pixels) ----
    const float2* kb2 = (const float2*)(k + base);
    const float2* vb2 = (const float2*)(v + base);
    float2 ka = kb2[(size_t)px0 * 128];
    float2 kb = kb2[(size_t)(px0 + 1) * 128];
    float2 va = vb2[(size_t)px0 * 128];          // prefetch v early
    float2 vb = vb2[(size_t)(px0 + 1) * 128];

    const float2 w2 = ((const float2*)w)[cp];
    const float2 u2 = ((const float2*)u)[cp];

    // ---- halo-only fill (exact-zero taps); disjoint from interior stores ----
    #pragma unroll
    for (int i = t; i < 2 * CSTRIDE; i += 128) {
        int pos = i & (CSTRIDE - 1);
        int row = pos / TW;
        int col = pos - row * TW;
        bool interior = (row >= PAD) & (row < PAD + 16) & (col >= PAD) & (col < PAD + 16);
        if (!interior) ks[i] = -1e30f;
    }

    // ---- interior stores ----
    const int pos0 = (y + PAD) * TW + (x0 + PAD);
    ks[pos0]               = ka.x;
    ks[pos0 + 1]           = kb.x;
    ks[CSTRIDE + pos0]     = ka.y;
    ks[CSTRIDE + pos0 + 1] = kb.y;

    // ---- per-channel max via full-warp shuffle reduce ----
    float m0 = fmaxf(ka.x, kb.x);
    float m1 = fmaxf(ka.y, kb.y);
    #pragma unroll
    for (int s = 16; s >= 1; s >>= 1) {
        m0 = fmaxf(m0, __shfl_xor_sync(0xffffffffu, m0, s));
        m1 = fmaxf(m1, __shfl_xor_sync(0xffffffffu, m1, s));
    }
    if ((t & 31) == 0) { red[t >> 5] = m0; red[4 + (t >> 5)] = m1; }

    __syncthreads();   // tile + red visible

    const float mm0 = fmaxf(fmaxf(red[0], red[1]), fmaxf(red[2], red[3]));
    const float mm1 = fmaxf(fmaxf(red[4], red[5]), fmaxf(red[6], red[7]));
    // all taps with d > r are exactly zero (w >= 0.3 > 0)
    const int r0 = (int)(fmaxf(mm0, 0.0f) / w2.x) + 1;
    const int r1 = (int)(fmaxf(mm1, 0.0f) / w2.y) + 1;
    const int r  = min(max(r0, r1), 30);

    const float wn0 = -w2.x, wn1 = -w2.y;
    float acc[4] = {0.f, 0.f, 0.f, 0.f};

    if (r <= PAD) {
        switch (r) {
            case 1:  diamond22<1>(ks, pos0, wn0, wn1, acc); break;
            case 2:  diamond22<2>(ks, pos0, wn0, wn1, acc); break;
            default: diamond22<3>(ks, pos0, wn0, wn1, acc); break;
        }
    } else {
        // generic bounds-checked fallback (rare)
        #pragma unroll
        for (int p = 0; p < 2; ++p) {
            int xx = x0 + p;
            float a0 = 0.f, a1 = 0.f;
            for (int di = -r; di <= r; ++di) {
                int iy = y + di;
                if ((unsigned)iy >= 16u) continue;
                int adi = di < 0 ? -di : di;
                int rr = r - adi;
                for (int dj = -rr; dj <= rr; ++dj) {
                    int ix = xx + dj;
                    if ((unsigned)ix >= 16u) continue;
                    int adj_ = dj < 0 ? -dj : dj;
                    float d = (float)(adi + adj_);
                    int pp = (iy + PAD) * TW + ix + PAD;
                    a0 += relu_(fmaf(wn0, d, ks[pp]));
                    a1 += relu_(fmaf(wn1, d, ks[CSTRIDE + pp]));
                }
            }
            acc[0 + p] = a0;
            acc[2 + p] = a1;
        }
    }

    // ---- center bonus (k values still in registers) + epilogue ----
    acc[0] += relu_(ka.x + u2.x) - relu_(ka.x);
    acc[1] += relu_(kb.x + u2.x) - relu_(kb.x);
    acc[2] += relu_(ka.y + u2.y) - relu_(ka.y);
    acc[3] += relu_(kb.y + u2.y) - relu_(kb.y);

    float2 o0, o1;
    o0.x = __expf(acc[0]) * va.x;
    o0.y = __expf(acc[2]) * va.y;
    o1.x = __expf(acc[1]) * vb.x;
    o1.y = __expf(acc[3]) * vb.y;

    float2* ob2 = (float2*)(out + base);
    ob2[(size_t)px0 * 128]       = o0;
    ob2[(size_t)(px0 + 1) * 128] = o1;
}

extern "C" void kernel_launch(void* const* d_in, const int* in_sizes, int n_in,
                              void* d_out, int out_size)
{
    const float *w = nullptr, *u = nullptr, *k = nullptr, *v = nullptr;
    for (int i = 0; i < n_in; i++) {
        if (in_sizes[i] == C_DIM) {
            if (!w) w = (const float*)d_in[i];
            else if (!u) u = (const float*)d_in[i];
        } else if (in_sizes[i] == B_DIM * 256 * C_DIM) {
            if (!k) k = (const float*)d_in[i];
            else if (!v) v = (const float*)d_in[i];
        }
    }
    wkv2d_kernel<<<B_DIM * (C_DIM / 2), 128>>>(w, u, k, v, (float*)d_out);
}

// round 4
// speedup vs baseline: 1.1179x; 1.1179x over previous
#include <cuda_runtime.h>
#include <cuda_bf16.h>
#include <cstddef>

// WKV2D: B=8, H=16, W=16, C=256.
// k_adj = sum_taps relu(k - w[c]*manhattan_d) (+u bonus at center); out = exp(k_adj)*v.
// Sparsity: taps with d > r = floor(kmax_c/w_c)+1 are exactly zero (w>0).
// Halo trick: -1e30 padding => relu gives exact 0, no bounds checks.
//
// Layout: block = 8 consecutive channels x whole 16x16 image of one batch.
// Thread (c = t&7, s = t>>3) owns 8 horizontally-consecutive pixels (half-row)
// of one channel -> every global access is a fully-utilized 32B sector.

#define B_DIM   8
#define C_DIM   256
#define CCH     8
#define PAD     3            // fast path covers r <= 3
#define TW      23           // padded row stride (16 + 2*PAD + 1)
#define TROWS   22           // 16 + 2*PAD
#define CPLANE  516          // 506 used; 516 % 32 == 4 -> max 2-way LDS conflict

__device__ __forceinline__ float relu_(float x) { return fmaxf(x, 0.0f); }

// 8 consecutive pixels of one channel, compile-time radius.
// Each tap-row segment is loaded once into registers and serves all 8 pixels.
template<int R>
__device__ __forceinline__ void diamond8(const float* __restrict__ ksb, int pos0,
                                         float wneg, float acc[8])
{
    float wd[2 * R + 1];
    #pragma unroll
    for (int d = 0; d <= 2 * R; ++d) wd[d] = wneg * (float)d;

    #pragma unroll
    for (int di = -R; di <= R; ++di) {
        const int adi = di < 0 ? -di : di;
        const int rr  = R - adi;
        float seg[8 + 2 * R];
        const int sbase = pos0 + di * TW - rr;
        #pragma unroll
        for (int j = 0; j < 8 + 2 * rr; ++j) seg[j] = ksb[sbase + j];
        #pragma unroll
        for (int i = 0; i < 8; ++i) {
            #pragma unroll
            for (int dj = -rr; dj <= rr; ++dj) {
                const int adj = dj < 0 ? -dj : dj;
                acc[i] += relu_(seg[i + dj + rr] + wd[adi + adj]);
            }
        }
    }
}

__global__ __launch_bounds__(256, 4)
void wkv2d_kernel(const float* __restrict__ w,
                  const float* __restrict__ u,
                  const float* __restrict__ k,
                  const float* __restrict__ v,
                  float* __restrict__ out)
{
    __shared__ float ks[CCH * CPLANE];   // 8 padded channel planes (~16.5KB)
    __shared__ float red[8 * CCH];       // [warp][c] partial maxes

    const int b  = blockIdx.x >> 5;      // 32 channel-chunks per batch
    const int c0 = (blockIdx.x & 31) * CCH;
    const int t  = threadIdx.x;
    const int c  = t & 7;
    const int s  = t >> 3;               // 0..31 : (y, half-row)
    const int y  = s >> 1;
    const int x0 = (s & 1) << 3;

    const size_t base = ((size_t)b * 256) * C_DIM + c0;
    const float* kg = k + base + c;
    const float* vg = v + base + c;
    const int px0 = (y << 4) + x0;

    // ---- issue all 16 global loads up front (MLP) ----
    float kr[8], vr[8];
    #pragma unroll
    for (int i = 0; i < 8; ++i) kr[i] = kg[(size_t)(px0 + i) * C_DIM];
    #pragma unroll
    for (int i = 0; i < 8; ++i) vr[i] = vg[(size_t)(px0 + i) * C_DIM];

    const float wv = w[c0 + c];
    const float uv = u[c0 + c];

    // ---- fill all planes with -1e30 (halo => exact zeros) ----
    #pragma unroll
    for (int i = t; i < CCH * CPLANE; i += 256) ks[i] = -1e30f;
    __syncthreads();

    // ---- interior stores + per-channel max ----
    float* ksb = ks + c * CPLANE;
    const int pos0 = (y + PAD) * TW + (x0 + PAD);
    float m = -1e30f;
    #pragma unroll
    for (int i = 0; i < 8; ++i) {
        ksb[pos0 + i] = kr[i];
        m = fmaxf(m, kr[i]);
    }
    // reduce over lanes with the same channel (xor 8, 16)
    m = fmaxf(m, __shfl_xor_sync(0xffffffffu, m, 8));
    m = fmaxf(m, __shfl_xor_sync(0xffffffffu, m, 16));
    if ((t & 31) < 8) red[(t >> 5) * CCH + c] = m;
    __syncthreads();

    float mm = -1e30f;
    #pragma unroll
    for (int ww = 0; ww < 8; ++ww) mm = fmaxf(mm, red[ww * CCH + c]);   // broadcast
    int rc = (int)(fmaxf(mm, 0.0f) / wv) + 1;    // taps with d > rc are exactly 0
    rc = min(rc, 30);
    const int r = __reduce_max_sync(0xffffffffu, rc);   // warp-uniform branch

    const float wneg = -wv;

    // ---- init acc with the center bonus (relu(k+u) replaces relu(k)) ----
    float acc[8];
    #pragma unroll
    for (int i = 0; i < 8; ++i)
        acc[i] = relu_(kr[i] + uv) - relu_(kr[i]);

    if (r <= PAD) {
        switch (r) {
            case 1:  diamond8<1>(ksb, pos0, wneg, acc); break;
            case 2:  diamond8<2>(ksb, pos0, wneg, acc); break;
            default: diamond8<3>(ksb, pos0, wneg, acc); break;
        }
    } else {
        // generic bounds-checked fallback (rare)
        #pragma unroll
        for (int i = 0; i < 8; ++i) {
            const int xx = x0 + i;
            float a = acc[i];
            for (int di = -r; di <= r; ++di) {
                int iy = y + di;
                if ((unsigned)iy >= 16u) continue;
                int adi = di < 0 ? -di : di;
                int rr = r - adi;
                for (int dj = -rr; dj <= rr; ++dj) {
                    int ix = xx + dj;
                    if ((unsigned)ix >= 16u) continue;
                    int adj_ = dj < 0 ? -dj : dj;
                    a += relu_(fmaf(wneg, (float)(adi + adj_),
                                    ksb[(iy + PAD) * TW + ix + PAD]));
                }
            }
            acc[i] = a;
        }
    }

    // ---- epilogue: fully-sectored stores ----
    float* og = out + base + c;
    #pragma unroll
    for (int i = 0; i < 8; ++i)
        og[(size_t)(px0 + i) * C_DIM] = __expf(acc[i]) * vr[i];
}

extern "C" void kernel_launch(void* const* d_in, const int* in_sizes, int n_in,
                              void* d_out, int out_size)
{
    const float *w = nullptr, *u = nullptr, *k = nullptr, *v = nullptr;
    for (int i = 0; i < n_in; i++) {
        if (in_sizes[i] == C_DIM) {
            if (!w) w = (const float*)d_in[i];
            else if (!u) u = (const float*)d_in[i];
        } else if (in_sizes[i] == B_DIM * 256 * C_DIM) {
            if (!k) k = (const float*)d_in[i];
            else if (!v) v = (const float*)d_in[i];
        }
    }
    wkv2d_kernel<<<B_DIM * (C_DIM / CCH), 256>>>(w, u, k, v, (float*)d_out);
}

// round 5
// speedup vs baseline: 1.1550x; 1.0332x over previous
#include <cuda_runtime.h>
#include <cuda_bf16.h>
#include <cstddef>

// WKV2D: B=8, H=16, W=16, C=256.
// k_adj = sum_taps relu(k - w[c]*manhattan_d) (+u bonus at center); out = exp(k_adj)*v.
// Sparsity: taps with d > r = floor(kmax_c/w_c)+1 are exactly zero (w>0).
// Halo trick: -1e30 padding => relu gives exact 0, no bounds checks.
//
// Block = 8 consecutive channels x whole 16x16 image of one batch; 512 threads.
// Thread (c = t&7, q = t>>3) owns 4 horizontally-consecutive pixels of one
// channel -> every global access is a fully-utilized 32B sector.

#define B_DIM   8
#define C_DIM   256
#define CCH     8
#define PAD     3            // fast path covers r <= 3
#define TW      23           // padded row stride
#define TROWS   22           // 16 + 2*PAD
#define CPLANE  514          // 506 used; 514 % 32 == 2 -> uniform 2-way worst case

__device__ __forceinline__ float relu_(float x) { return fmaxf(x, 0.0f); }

// 4 consecutive pixels of one channel, compile-time radius.
// Each tap-row segment is loaded once into registers and serves all 4 pixels.
template<int R>
__device__ __forceinline__ void diamond4(const float* __restrict__ ksb, int pos0,
                                         float wneg, float acc[4])
{
    float wd[2 * R + 1];
    #pragma unroll
    for (int d = 0; d <= 2 * R; ++d) wd[d] = wneg * (float)d;

    #pragma unroll
    for (int di = -R; di <= R; ++di) {
        const int adi = di < 0 ? -di : di;
        const int rr  = R - adi;
        float seg[4 + 2 * R];
        const int sbase = pos0 + di * TW - rr;
        #pragma unroll
        for (int j = 0; j < 4 + 2 * rr; ++j) seg[j] = ksb[sbase + j];
        #pragma unroll
        for (int i = 0; i < 4; ++i) {
            #pragma unroll
            for (int dj = -rr; dj <= rr; ++dj) {
                const int adj = dj < 0 ? -dj : dj;
                acc[i] += relu_(seg[i + dj + rr] + wd[adi + adj]);
            }
        }
    }
}

__global__ __launch_bounds__(512, 2)
void wkv2d_kernel(const float* __restrict__ w,
                  const float* __restrict__ u,
                  const float* __restrict__ k,
                  const float* __restrict__ v,
                  float* __restrict__ out)
{
    __shared__ float ks[CCH * CPLANE];   // 8 padded channel planes (~16.4KB)
    __shared__ float red[16 * CCH];      // [warp][c] partial maxes

    const int b  = blockIdx.x >> 5;      // 32 channel-chunks per batch
    const int c0 = (blockIdx.x & 31) * CCH;
    const int t  = threadIdx.x;
    const int c  = t & 7;
    const int q  = t >> 3;               // 0..63 : quarter-row index
    const int y  = q >> 2;
    const int x0 = (q & 3) << 2;

    const size_t base = ((size_t)b * 256) * C_DIM + c0;
    const float* kg = k + base + c;
    const float* vg = v + base + c;
    const int px0 = (y << 4) + x0;

    // ---- issue all 8 global loads up front (MLP) ----
    float kr[4], vr[4];
    #pragma unroll
    for (int i = 0; i < 4; ++i) kr[i] = kg[(size_t)(px0 + i) * C_DIM];
    #pragma unroll
    for (int i = 0; i < 4; ++i) vr[i] = vg[(size_t)(px0 + i) * C_DIM];

    const float wv = w[c0 + c];
    const float uv = u[c0 + c];

    // ---- halo-only fill: disjoint from interior stores, so no extra sync ----
    #pragma unroll
    for (int p = 0; p < CCH; ++p) {
        int pos = t;
        int row = pos / TW;
        int col = pos - row * TW;
        bool interior = (row >= PAD) & (row < PAD + 16) & (col >= PAD) & (col < PAD + 16);
        if (!interior) ks[p * CPLANE + pos] = -1e30f;
        if (t < CPLANE - 512) ks[p * CPLANE + 512 + t] = -1e30f;  // tail positions
    }

    // ---- interior stores + per-channel partial max ----
    float* ksb = ks + c * CPLANE;
    const int pos0 = (y + PAD) * TW + (x0 + PAD);
    float m = fmaxf(fmaxf(kr[0], kr[1]), fmaxf(kr[2], kr[3]));
    #pragma unroll
    for (int i = 0; i < 4; ++i) ksb[pos0 + i] = kr[i];

    // reduce over lanes with the same channel (xor 8, 16)
    m = fmaxf(m, __shfl_xor_sync(0xffffffffu, m, 8));
    m = fmaxf(m, __shfl_xor_sync(0xffffffffu, m, 16));
    if ((t & 31) < 8) red[(t >> 5) * CCH + c] = m;

    __syncthreads();   // single barrier: tile + red both visible

    float mm = -1e30f;
    #pragma unroll
    for (int ww = 0; ww < 16; ++ww)
        mm = fmaxf(mm, red[ww * CCH + c]);              // broadcast LDS
    int rc = (int)(fmaxf(mm, 0.0f) / wv) + 1;           // taps with d > rc are exactly 0
    rc = min(rc, 30);
    const int r = __reduce_max_sync(0xffffffffu, rc);   // warp-uniform branch

    const float wneg = -wv;

    // ---- init acc with the center bonus (relu(k+u) replaces relu(k)) ----
    float acc[4];
    #pragma unroll
    for (int i = 0; i < 4; ++i)
        acc[i] = relu_(kr[i] + uv) - relu_(kr[i]);

    if (r <= PAD) {
        switch (r) {
            case 1:  diamond4<1>(ksb, pos0, wneg, acc); break;
            case 2:  diamond4<2>(ksb, pos0, wneg, acc); break;
            default: diamond4<3>(ksb, pos0, wneg, acc); break;
        }
    } else {
        // generic bounds-checked fallback (rare)
        #pragma unroll
        for (int i = 0; i < 4; ++i) {
            const int xx = x0 + i;
            float a = acc[i];
            for (int di = -r; di <= r; ++di) {
                int iy = y + di;
                if ((unsigned)iy >= 16u) continue;
                int adi = di < 0 ? -di : di;
                int rr = r - adi;
                for (int dj = -rr; dj <= rr; ++dj) {
                    int ix = xx + dj;
                    if ((unsigned)ix >= 16u) continue;
                    int adj_ = dj < 0 ? -dj : dj;
                    a += relu_(fmaf(wneg, (float)(adi + adj_),
                                    ksb[(iy + PAD) * TW + ix + PAD]));
                }
            }
            acc[i] = a;
        }
    }

    // ---- epilogue: fully-sectored stores ----
    float* og = out + base + c;
    #pragma unroll
    for (int i = 0; i < 4; ++i)
        og[(size_t)(px0 + i) * C_DIM] = __expf(acc[i]) * vr[i];
}

extern "C" void kernel_launch(void* const* d_in, const int* in_sizes, int n_in,
                              void* d_out, int out_size)
{
    const float *w = nullptr, *u = nullptr, *k = nullptr, *v = nullptr;
    for (int i = 0; i < n_in; i++) {
        if (in_sizes[i] == C_DIM) {
            if (!w) w = (const float*)d_in[i];
            else if (!u) u = (const float*)d_in[i];
        } else if (in_sizes[i] == B_DIM * 256 * C_DIM) {
            if (!k) k = (const float*)d_in[i];
            else if (!v) v = (const float*)d_in[i];
        }
    }
    wkv2d_kernel<<<B_DIM * (C_DIM / CCH), 512>>>(w, u, k, v, (float*)d_out);
}